// round 5
// baseline (speedup 1.0000x reference)
#include <cuda_runtime.h>
#include <cuda_bf16.h>
#include <math.h>

#define N_NODES 50000
#define N_EDGES 600000
#define IN_DIM  128
#define HID     128
#define OUT_DIM 64
#define LN_EPS  1e-5f

// ---------------- scratch (device globals; no allocation allowed) ----------------
__device__ int   g_deg_out[N_NODES];
__device__ int   g_deg_in [N_NODES];
__device__ float g_out_norm[N_NODES];
__device__ float g_in_norm [N_NODES];
__device__ int   g_row_off[N_NODES + 1];
__device__ int   g_cursor [N_NODES];
__device__ int   g_edge_src[N_EDGES];
__device__ float g_tbuf[(size_t)N_NODES * HID];
__device__ float g_hbuf[(size_t)N_NODES * HID];

// ---------------- small setup kernels ----------------
__global__ void init_kernel() {
    int i = blockIdx.x * blockDim.x + threadIdx.x;
    if (i < N_NODES) { g_deg_out[i] = 0; g_deg_in[i] = 0; }
}

__global__ void degree_kernel(const int* __restrict__ src, const int* __restrict__ dst) {
    int e = blockIdx.x * blockDim.x + threadIdx.x;
    if (e < N_EDGES) {
        atomicAdd(&g_deg_out[src[e]], 1);
        atomicAdd(&g_deg_in [dst[e]], 1);
    }
}

__global__ void norm_kernel() {
    int i = blockIdx.x * blockDim.x + threadIdx.x;
    if (i < N_NODES) {
        g_out_norm[i] = rsqrtf(fmaxf((float)g_deg_out[i], 1.0f));
        g_in_norm [i] = rsqrtf(fmaxf((float)g_deg_in [i], 1.0f));
    }
}

// thread-coarsened single-block exclusive scan: g_deg_in -> g_row_off, g_cursor
__global__ void scan_kernel() {
    constexpr int T  = 1024;
    constexpr int CH = (N_NODES + T - 1) / T;   // 49
    __shared__ int wsum[32];
    int tid  = threadIdx.x;
    int lane = tid & 31, wid = tid >> 5;
    int base = tid * CH;

    int s = 0;
    #pragma unroll 7
    for (int i = 0; i < CH; ++i) {
        int idx = base + i;
        if (idx < N_NODES) s += g_deg_in[idx];
    }
    // block inclusive scan of per-thread sums
    int x = s;
    #pragma unroll
    for (int off = 1; off < 32; off <<= 1) {
        int y = __shfl_up_sync(0xFFFFFFFFu, x, off);
        if (lane >= off) x += y;
    }
    if (lane == 31) wsum[wid] = x;
    __syncthreads();
    if (wid == 0) {
        int w = wsum[lane];
        #pragma unroll
        for (int off = 1; off < 32; off <<= 1) {
            int y = __shfl_up_sync(0xFFFFFFFFu, w, off);
            if (lane >= off) w += y;
        }
        wsum[lane] = w;
    }
    __syncthreads();
    int run = (wid > 0 ? wsum[wid - 1] : 0) + (x - s);   // exclusive prefix at chunk start
    #pragma unroll 7
    for (int i = 0; i < CH; ++i) {
        int idx = base + i;
        if (idx < N_NODES) {
            g_row_off[idx] = run;
            g_cursor [idx] = run;
            run += g_deg_in[idx];
        }
    }
    if (tid == T - 1) g_row_off[N_NODES] = run;
}

__global__ void fill_kernel(const int* __restrict__ src, const int* __restrict__ dst) {
    int e = blockIdx.x * blockDim.x + threadIdx.x;
    if (e < N_EDGES) {
        int d = dst[e];
        int pos = atomicAdd(&g_cursor[d], 1);
        g_edge_src[pos] = src[e];
    }
}

// ---------------- tf32 tensor-core GEMM with 3xTF32 split ----------------
// T[row,:] = (H[row,:] * out_norm[row]) @ W ;  K = 128.
// Block tile 128 x DOUT, 256 threads (8 warps). Fragments staged in smem in
// mma-fragment order (conflict-free float4/float2 LDS in the hot loop).

__device__ __forceinline__ void split_tf32(float v, float& hi_out, float& lo_out) {
    unsigned hi;
    asm("cvt.rna.tf32.f32 %0, %1;" : "=r"(hi) : "f"(v));
    float hif = __uint_as_float(hi);
    float lof = v - hif;
    unsigned lo;
    asm("cvt.rna.tf32.f32 %0, %1;" : "=r"(lo) : "f"(lof));
    hi_out = hif;
    lo_out = __uint_as_float(lo);
}

__device__ __forceinline__ void mma_tf32(float* c, const float4& a, const float2& b) {
    asm volatile(
        "mma.sync.aligned.m16n8k8.row.col.f32.tf32.tf32.f32 "
        "{%0,%1,%2,%3}, {%4,%5,%6,%7}, {%8,%9}, {%0,%1,%2,%3};"
        : "+f"(c[0]), "+f"(c[1]), "+f"(c[2]), "+f"(c[3])
        : "r"(__float_as_uint(a.x)), "r"(__float_as_uint(a.y)),
          "r"(__float_as_uint(a.z)), "r"(__float_as_uint(a.w)),
          "r"(__float_as_uint(b.x)), "r"(__float_as_uint(b.y)));
}

template <int DOUT>
__global__ __launch_bounds__(256)
void gemm_tc_kernel(const float* __restrict__ H, const float* __restrict__ W,
                    float* __restrict__ T) {
    constexpr int BM  = 128, KC = 32, K = 128;
    constexpr int NB8 = DOUT / 8;
    constexpr int ASZ = BM * KC;       // 4096 floats
    constexpr int BSZ = KC * DOUT;     // 4096 / 2048 floats
    constexpr int MT  = (DOUT == 128) ? 2 : 1;   // 16-row tiles per warp
    constexpr int NT  = 8;                        // 8-col tiles per warp (WN=64)

    extern __shared__ float sm[];
    float* As_hi = sm;
    float* As_lo = As_hi + ASZ;
    float* Bs_hi = As_lo + ASZ;
    float* Bs_lo = Bs_hi + BSZ;

    const int tid  = threadIdx.x;
    const int lane = tid & 31;
    const int wid  = tid >> 5;
    const int row0 = blockIdx.x * BM;

    int wm0, wn0;
    if (DOUT == 128) { wm0 = (wid & 3) * 32; wn0 = (wid >> 2) * 64; }
    else             { wm0 = wid * 16;       wn0 = 0;               }

    float acc[MT][NT][4];
    #pragma unroll
    for (int mt = 0; mt < MT; ++mt)
        #pragma unroll
        for (int nt = 0; nt < NT; ++nt)
            #pragma unroll
            for (int j = 0; j < 4; ++j) acc[mt][nt][j] = 0.0f;

    for (int kc = 0; kc < K; kc += KC) {
        // ---- stage A chunk (scaled by out_norm) into fragment-order smem ----
        #pragma unroll
        for (int l = 0; l < ASZ / 4 / 256; ++l) {          // 4 float4 per thread
            int idx = tid + l * 256;                        // float4 id
            int r   = idx >> 3;                             // 0..127
            int k4  = idx & 7;
            int row = row0 + r;
            float4 v = make_float4(0.f, 0.f, 0.f, 0.f);
            if (row < N_NODES) {
                v = *(const float4*)&H[(size_t)row * K + kc + k4 * 4];
                float nm = g_out_norm[row];
                v.x *= nm; v.y *= nm; v.z *= nm; v.w *= nm;
            }
            float vv[4] = {v.x, v.y, v.z, v.w};
            int im = r >> 4, rr = r & 15;
            #pragma unroll
            for (int c = 0; c < 4; ++c) {
                int kl = k4 * 4 + c;
                int ik = kl >> 3, kk = kl & 7, tg = kk & 3;
                int tp = (rr & 7) * 4 + tg;
                int j  = (rr >> 3) + ((kk >> 2) << 1);
                int f  = ((ik * 8 + im) * 32 + tp) * 4 + j;
                split_tf32(vv[c], As_hi[f], As_lo[f]);
            }
        }
        // ---- stage B chunk into fragment-order smem ----
        #pragma unroll
        for (int l = 0; l < BSZ / 4 / 256; ++l) {
            int idx = tid + l * 256;
            int kr  = idx / (DOUT / 4);
            int n4  = idx % (DOUT / 4);
            float4 v = *(const float4*)&W[(size_t)(kc + kr) * DOUT + n4 * 4];
            float vv[4] = {v.x, v.y, v.z, v.w};
            int kk = kr & 7, ik = kr >> 3, tg = kk & 3, jb = kk >> 2;
            #pragma unroll
            for (int c = 0; c < 4; ++c) {
                int n  = n4 * 4 + c;
                int n8 = n >> 3, g = n & 7;
                int tp = g * 4 + tg;
                int f  = ((ik * NB8 + n8) * 32 + tp) * 2 + jb;
                split_tf32(vv[c], Bs_hi[f], Bs_lo[f]);
            }
        }
        __syncthreads();

        // ---- compute ----
        #pragma unroll
        for (int ik = 0; ik < KC / 8; ++ik) {
            float4 ah[MT], al[MT];
            #pragma unroll
            for (int mt = 0; mt < MT; ++mt) {
                int im = (wm0 >> 4) + mt;
                ah[mt] = *(const float4*)&As_hi[((ik * 8 + im) * 32 + lane) * 4];
                al[mt] = *(const float4*)&As_lo[((ik * 8 + im) * 32 + lane) * 4];
            }
            #pragma unroll
            for (int nt = 0; nt < NT; ++nt) {
                int n8 = (wn0 >> 3) + nt;
                float2 bh = *(const float2*)&Bs_hi[((ik * NB8 + n8) * 32 + lane) * 2];
                float2 bl = *(const float2*)&Bs_lo[((ik * NB8 + n8) * 32 + lane) * 2];
                #pragma unroll
                for (int mt = 0; mt < MT; ++mt) {
                    mma_tf32(acc[mt][nt], ah[mt], bh);   // hi*hi
                    mma_tf32(acc[mt][nt], ah[mt], bl);   // hi*lo
                    mma_tf32(acc[mt][nt], al[mt], bh);   // lo*hi
                }
            }
        }
        __syncthreads();
    }

    // ---- store ----
    const int g = lane >> 2, tg = lane & 3;
    #pragma unroll
    for (int mt = 0; mt < MT; ++mt) {
        #pragma unroll
        for (int nt = 0; nt < NT; ++nt) {
            int row_a = row0 + wm0 + mt * 16 + g;
            int col   = wn0 + nt * 8 + tg * 2;
            if (row_a < N_NODES)
                *(float2*)&T[(size_t)row_a * DOUT + col] =
                    make_float2(acc[mt][nt][0], acc[mt][nt][1]);
            int row_b = row_a + 8;
            if (row_b < N_NODES)
                *(float2*)&T[(size_t)row_b * DOUT + col] =
                    make_float2(acc[mt][nt][2], acc[mt][nt][3]);
        }
    }
}

// ---------------- aggregate: out[v] = epi( sum_{e in in(v)} T[src_e] * in_norm[v] + b )
// blockDim.x == D, blockDim.y nodes per block.
template <int D, int NY, bool LN>
__global__ void aggregate_kernel(const float* __restrict__ T, float* __restrict__ out,
                                 const float* __restrict__ bias,
                                 const float* __restrict__ ln_scale,
                                 const float* __restrict__ ln_bias) {
    int v = blockIdx.x * NY + threadIdx.y;
    int tid = threadIdx.x;
    const int s = g_row_off[v], e = g_row_off[v + 1];

    float acc = 0.0f;
    int i = s;
    for (; i + 4 <= e; i += 4) {
        int u0 = g_edge_src[i + 0];
        int u1 = g_edge_src[i + 1];
        int u2 = g_edge_src[i + 2];
        int u3 = g_edge_src[i + 3];
        float v0 = T[(size_t)u0 * D + tid];
        float v1 = T[(size_t)u1 * D + tid];
        float v2 = T[(size_t)u2 * D + tid];
        float v3 = T[(size_t)u3 * D + tid];
        acc += v0; acc += v1; acc += v2; acc += v3;
    }
    for (; i < e; ++i) acc += T[(size_t)g_edge_src[i] * D + tid];

    float val = fmaxf(acc * g_in_norm[v] + bias[tid], 0.0f);

    if (LN) {
        constexpr int NW = D / 32;
        float s1 = val, s2 = val * val;
        #pragma unroll
        for (int off = 16; off > 0; off >>= 1) {
            s1 += __shfl_xor_sync(0xFFFFFFFFu, s1, off);
            s2 += __shfl_xor_sync(0xFFFFFFFFu, s2, off);
        }
        __shared__ float sh1[NY][NW], sh2[NY][NW];
        int w = tid >> 5;
        if ((tid & 31) == 0) { sh1[threadIdx.y][w] = s1; sh2[threadIdx.y][w] = s2; }
        __syncthreads();
        float t1 = 0.f, t2 = 0.f;
        #pragma unroll
        for (int j = 0; j < NW; ++j) { t1 += sh1[threadIdx.y][j]; t2 += sh2[threadIdx.y][j]; }
        float mu  = t1 * (1.0f / D);
        float var = t2 * (1.0f / D) - mu * mu;
        val = (val - mu) * rsqrtf(var + LN_EPS) * ln_scale[tid] + ln_bias[tid];
    }
    out[(size_t)v * D + tid] = val;
}

// ---------------- launch ----------------
extern "C" void kernel_launch(void* const* d_in, const int* in_sizes, int n_in,
                              void* d_out, int out_size) {
    const float* x        = (const float*)d_in[0];
    const int*   src      = (const int*)  d_in[1];
    const int*   dst      = (const int*)  d_in[2];
    const float* W0       = (const float*)d_in[3];
    const float* b0       = (const float*)d_in[4];
    const float* W1       = (const float*)d_in[5];
    const float* b1       = (const float*)d_in[6];
    const float* W2       = (const float*)d_in[7];
    const float* b2       = (const float*)d_in[8];
    const float* ln_scale = (const float*)d_in[9];
    const float* ln_bias  = (const float*)d_in[10];
    float* out = (float*)d_out;

    float* tbuf; cudaGetSymbolAddress((void**)&tbuf, g_tbuf);
    float* hbuf; cudaGetSymbolAddress((void**)&hbuf, g_hbuf);

    const int EBLK = (N_EDGES + 255) / 256;
    const int NBLK = (N_NODES + 255) / 256;
    const int GBLK = (N_NODES + 127) / 128;

    const int SMEM128 = (2 * 4096 + 2 * 4096) * 4;   // 64 KB
    const int SMEM64  = (2 * 4096 + 2 * 2048) * 4;   // 48 KB
    cudaFuncSetAttribute(gemm_tc_kernel<HID>,
                         cudaFuncAttributeMaxDynamicSharedMemorySize, SMEM128);
    cudaFuncSetAttribute(gemm_tc_kernel<OUT_DIM>,
                         cudaFuncAttributeMaxDynamicSharedMemorySize, SMEM64);

    // graph preprocessing (recomputed every call; deterministic work)
    init_kernel  <<<NBLK, 256>>>();
    degree_kernel<<<EBLK, 256>>>(src, dst);
    norm_kernel  <<<NBLK, 256>>>();
    scan_kernel  <<<1, 1024>>>();
    fill_kernel  <<<EBLK, 256>>>(src, dst);

    // layer 0: x -> tbuf -> hbuf (relu + LN)
    gemm_tc_kernel<HID><<<GBLK, 256, SMEM128>>>(x, W0, tbuf);
    aggregate_kernel<HID, 2, true><<<N_NODES / 2, dim3(HID, 2)>>>(tbuf, hbuf, b0, ln_scale, ln_bias);

    // layer 1: hbuf -> tbuf -> hbuf (relu + LN)
    gemm_tc_kernel<HID><<<GBLK, 256, SMEM128>>>(hbuf, W1, tbuf);
    aggregate_kernel<HID, 2, true><<<N_NODES / 2, dim3(HID, 2)>>>(tbuf, hbuf, b1, ln_scale, ln_bias);

    // layer 2: hbuf -> tbuf -> out (relu, no LN)
    gemm_tc_kernel<OUT_DIM><<<GBLK, 256, SMEM64>>>(hbuf, W2, tbuf);
    aggregate_kernel<OUT_DIM, 4, false><<<N_NODES / 4, dim3(OUT_DIM, 4)>>>(tbuf, out, b2, ln_scale, ln_bias);

    (void)in_sizes; (void)n_in; (void)out_size;
}

// round 6
// speedup vs baseline: 2.6216x; 2.6216x over previous
#include <cuda_runtime.h>
#include <cuda_bf16.h>
#include <math.h>

#define N_NODES 50000
#define N_EDGES 600000
#define IN_DIM  128
#define HID     128
#define OUT_DIM 64
#define LN_EPS  1e-5f

#define SCAN_BS   256
#define SCAN_NB   ((N_NODES + SCAN_BS - 1) / SCAN_BS)   // 196

// ---------------- scratch (device globals; no allocation allowed) ----------------
__device__ int   g_deg_out[N_NODES];
__device__ int   g_deg_in [N_NODES];
__device__ float g_out_norm[N_NODES];
__device__ float g_in_norm [N_NODES];
__device__ int   g_row_off[N_NODES + 1];
__device__ int   g_cursor [N_NODES];
__device__ int   g_edge_src[N_EDGES];
__device__ int   g_part[SCAN_BS];
__device__ float g_tbuf[(size_t)N_NODES * HID];
__device__ float g_hbuf[(size_t)N_NODES * HID];

// ---------------- small setup kernels ----------------
__global__ void init_kernel() {
    int i = blockIdx.x * blockDim.x + threadIdx.x;
    if (i < N_NODES) { g_deg_out[i] = 0; g_deg_in[i] = 0; }
}

__global__ void degree_kernel(const int* __restrict__ src, const int* __restrict__ dst) {
    int e = blockIdx.x * blockDim.x + threadIdx.x;
    if (e < N_EDGES) {
        atomicAdd(&g_deg_out[src[e]], 1);
        atomicAdd(&g_deg_in [dst[e]], 1);
    }
}

__global__ void norm_kernel() {
    int i = blockIdx.x * blockDim.x + threadIdx.x;
    if (i < N_NODES) {
        g_out_norm[i] = rsqrtf(fmaxf((float)g_deg_out[i], 1.0f));
        g_in_norm [i] = rsqrtf(fmaxf((float)g_deg_in [i], 1.0f));
    }
}

// block-wide inclusive scan of one value per thread (256 threads)
__device__ __forceinline__ int block_incl_scan(int v, int* wsum) {
    int lane = threadIdx.x & 31, wid = threadIdx.x >> 5;
    int x = v;
    #pragma unroll
    for (int off = 1; off < 32; off <<= 1) {
        int y = __shfl_up_sync(0xFFFFFFFFu, x, off);
        if (lane >= off) x += y;
    }
    if (lane == 31) wsum[wid] = x;
    __syncthreads();
    if (wid == 0 && lane < 8) {
        int w = wsum[lane];
        #pragma unroll
        for (int off = 1; off < 8; off <<= 1) {
            int y = __shfl_up_sync(0xFFu, w, off);
            if (lane >= off) w += y;
        }
        wsum[lane] = w;
    }
    __syncthreads();
    return x + (wid > 0 ? wsum[wid - 1] : 0);
}

// pass 1: per-block sums of deg_in
__global__ void scan1_kernel() {
    __shared__ int wsum[8];
    int i = blockIdx.x * SCAN_BS + threadIdx.x;
    int v = (i < N_NODES) ? g_deg_in[i] : 0;
    int incl = block_incl_scan(v, wsum);
    if (threadIdx.x == SCAN_BS - 1) g_part[blockIdx.x] = incl;
}

// pass 2: exclusive scan of the 196 block sums (single small block)
__global__ void scan2_kernel() {
    __shared__ int wsum[8];
    int t = threadIdx.x;
    int v = (t < SCAN_NB) ? g_part[t] : 0;
    int incl = block_incl_scan(v, wsum);
    if (t < SCAN_NB) g_part[t] = incl - v;      // exclusive
    if (t == 0) g_row_off[N_NODES] = N_EDGES;
}

// pass 3: final offsets
__global__ void scan3_kernel() {
    __shared__ int wsum[8];
    int i = blockIdx.x * SCAN_BS + threadIdx.x;
    int v = (i < N_NODES) ? g_deg_in[i] : 0;
    int incl = block_incl_scan(v, wsum);
    if (i < N_NODES) {
        int off = g_part[blockIdx.x] + incl - v;
        g_row_off[i] = off;
        g_cursor [i] = off;
    }
}

__global__ void fill_kernel(const int* __restrict__ src, const int* __restrict__ dst) {
    int e = blockIdx.x * blockDim.x + threadIdx.x;
    if (e < N_EDGES) {
        int d = dst[e];
        int pos = atomicAdd(&g_cursor[d], 1);
        g_edge_src[pos] = src[e];
    }
}

// ---------------- 3xBF16 tensor-core GEMM ----------------
// T[row,:] = (H[row,:] * out_norm[row]) @ W ; K = 128.
// Block: 64 rows, 256 threads (8 warps). Whole-K fragment staging in smem,
// bf16 hi/lo split: a*b ~= ah*bh + ah*bl + al*bh (fp32 accumulate).

__device__ __forceinline__ void split_pair(float a, float b, unsigned& hi, unsigned& lo) {
    __nv_bfloat16 ah = __float2bfloat16_rn(a);
    __nv_bfloat16 bh = __float2bfloat16_rn(b);
    float ar = a - __bfloat162float(ah);
    float br = b - __bfloat162float(bh);
    __nv_bfloat16 al = __float2bfloat16_rn(ar);
    __nv_bfloat16 bl = __float2bfloat16_rn(br);
    hi = (unsigned)__bfloat16_as_ushort(ah) | ((unsigned)__bfloat16_as_ushort(bh) << 16);
    lo = (unsigned)__bfloat16_as_ushort(al) | ((unsigned)__bfloat16_as_ushort(bl) << 16);
}

__device__ __forceinline__ void mma_bf16(float* c, const uint4& a, const uint2& b) {
    asm volatile(
        "mma.sync.aligned.m16n8k16.row.col.f32.bf16.bf16.f32 "
        "{%0,%1,%2,%3}, {%4,%5,%6,%7}, {%8,%9}, {%0,%1,%2,%3};"
        : "+f"(c[0]), "+f"(c[1]), "+f"(c[2]), "+f"(c[3])
        : "r"(a.x), "r"(a.y), "r"(a.z), "r"(a.w), "r"(b.x), "r"(b.y));
}

template <int DOUT>
__global__ __launch_bounds__(256)
void gemm_bf16_kernel(const float* __restrict__ H, const float* __restrict__ W,
                      float* __restrict__ T) {
    constexpr int K    = 128;
    constexpr int BM   = 64;
    constexpr int NWM  = BM / 16;          // 4 m-tiles
    constexpr int NB8  = DOUT / 8;         // n-tiles total (16 or 8)
    constexpr int NT   = NB8 / 2;          // n-tiles per warp (8 or 4)
    constexpr int NKT  = K / 16;           // 8 k-tiles

    extern __shared__ unsigned char smraw[];
    uint4* As_hi = (uint4*)smraw;                   // NWM*NKT*32
    uint4* As_lo = As_hi + NWM * NKT * 32;
    uint2* Bs_hi = (uint2*)(As_lo + NWM * NKT * 32);
    uint2* Bs_lo = Bs_hi + NKT * NB8 * 32;

    const int tid  = threadIdx.x;
    const int lane = tid & 31;
    const int w    = tid >> 5;
    const int g    = lane >> 2;
    const int t    = lane & 3;
    const int row0 = blockIdx.x * BM;

    // ---- stage A (scaled by out_norm) as fragment-packed bf16 hi/lo ----
    // thread (warp w = k-tile ik, lane) handles all NWM m-tiles
    #pragma unroll
    for (int mt = 0; mt < NWM; ++mt) {
        const int ik = w;
        const int kc = ik * 16 + t * 2;
        const int r0 = row0 + mt * 16 + g;
        const int r1 = r0 + 8;
        float2 x0 = make_float2(0.f, 0.f), x2 = x0, x1 = x0, x3 = x0;
        if (r0 < N_NODES) {
            float nm = g_out_norm[r0];
            x0 = *(const float2*)&H[(size_t)r0 * K + kc];
            x2 = *(const float2*)&H[(size_t)r0 * K + kc + 8];
            x0.x *= nm; x0.y *= nm; x2.x *= nm; x2.y *= nm;
        }
        if (r1 < N_NODES) {
            float nm = g_out_norm[r1];
            x1 = *(const float2*)&H[(size_t)r1 * K + kc];
            x3 = *(const float2*)&H[(size_t)r1 * K + kc + 8];
            x1.x *= nm; x1.y *= nm; x3.x *= nm; x3.y *= nm;
        }
        unsigned h0, l0, h1, l1, h2, l2, h3, l3;
        split_pair(x0.x, x0.y, h0, l0);   // a0: row g,   k, k+1
        split_pair(x1.x, x1.y, h1, l1);   // a1: row g+8, k, k+1
        split_pair(x2.x, x2.y, h2, l2);   // a2: row g,   k+8, k+9
        split_pair(x3.x, x3.y, h3, l3);   // a3: row g+8, k+8, k+9
        As_hi[(mt * NKT + ik) * 32 + lane] = make_uint4(h0, h1, h2, h3);
        As_lo[(mt * NKT + ik) * 32 + lane] = make_uint4(l0, l1, l2, l3);
    }

    // ---- stage W as fragment-packed bf16 hi/lo ----
    #pragma unroll
    for (int l = 0; l < NB8; ++l) {
        int idx = l * 256 + tid;
        int ik  = idx / (NB8 * 32);
        int n8  = (idx >> 5) % NB8;
        int ln  = idx & 31;
        int gg  = ln >> 2, tt = ln & 3;
        int n   = n8 * 8 + gg;
        int kc  = ik * 16 + tt * 2;
        float w0 = W[(size_t)(kc    ) * DOUT + n];
        float w1 = W[(size_t)(kc + 1) * DOUT + n];
        float w2 = W[(size_t)(kc + 8) * DOUT + n];
        float w3 = W[(size_t)(kc + 9) * DOUT + n];
        unsigned bh0, bl0, bh1, bl1;
        split_pair(w0, w1, bh0, bl0);     // b0: k, k+1   @ col n
        split_pair(w2, w3, bh1, bl1);     // b1: k+8, k+9 @ col n
        Bs_hi[(ik * NB8 + n8) * 32 + ln] = make_uint2(bh0, bh1);
        Bs_lo[(ik * NB8 + n8) * 32 + ln] = make_uint2(bl0, bl1);
    }
    __syncthreads();

    // ---- compute: warp = (m-tile, n-half) ----
    const int mtile = w & 3;
    const int nbase = (w >> 2) * NT;

    float acc[NT][4];
    #pragma unroll
    for (int nt = 0; nt < NT; ++nt)
        #pragma unroll
        for (int j = 0; j < 4; ++j) acc[nt][j] = 0.0f;

    #pragma unroll
    for (int ik = 0; ik < NKT; ++ik) {
        uint4 ah = As_hi[(mtile * NKT + ik) * 32 + lane];
        uint4 al = As_lo[(mtile * NKT + ik) * 32 + lane];
        #pragma unroll
        for (int nt = 0; nt < NT; ++nt) {
            uint2 bh = Bs_hi[(ik * NB8 + nbase + nt) * 32 + lane];
            uint2 bl = Bs_lo[(ik * NB8 + nbase + nt) * 32 + lane];
            mma_bf16(acc[nt], ah, bh);    // hi*hi
            mma_bf16(acc[nt], ah, bl);    // hi*lo
            mma_bf16(acc[nt], al, bh);    // lo*hi
        }
    }

    // ---- store ----
    #pragma unroll
    for (int nt = 0; nt < NT; ++nt) {
        int row_a = row0 + mtile * 16 + g;
        int col   = (nbase + nt) * 8 + t * 2;
        if (row_a < N_NODES)
            *(float2*)&T[(size_t)row_a * DOUT + col] = make_float2(acc[nt][0], acc[nt][1]);
        int row_b = row_a + 8;
        if (row_b < N_NODES)
            *(float2*)&T[(size_t)row_b * DOUT + col] = make_float2(acc[nt][2], acc[nt][3]);
    }
}

// ---------------- aggregation: warp per node, vectorized gather ----------------
// out[v] = epi( (sum_{e in in(v)} T[src_e]) * in_norm[v] + b )
template <int D, bool LN>
__global__ __launch_bounds__(256)
void aggregate_warp_kernel(const float* __restrict__ T, float* __restrict__ out,
                           const float* __restrict__ bias,
                           const float* __restrict__ ln_scale,
                           const float* __restrict__ ln_bias) {
    constexpr int VC = D / 32;                    // 4 (D=128) or 2 (D=64)
    const int lane = threadIdx.x & 31;
    const int v    = blockIdx.x * 8 + (threadIdx.x >> 5);
    const int s = g_row_off[v], e = g_row_off[v + 1];

    float acc[VC];
    #pragma unroll
    for (int c = 0; c < VC; ++c) acc[c] = 0.0f;

    for (int base = s; base < e; base += 32) {
        int rem = e - base;
        int n = rem < 32 ? rem : 32;
        int id = (lane < n) ? g_edge_src[base + lane] : 0;
        int j = 0;
        for (; j + 4 <= n; j += 4) {
            int u0 = __shfl_sync(0xFFFFFFFFu, id, j);
            int u1 = __shfl_sync(0xFFFFFFFFu, id, j + 1);
            int u2 = __shfl_sync(0xFFFFFFFFu, id, j + 2);
            int u3 = __shfl_sync(0xFFFFFFFFu, id, j + 3);
            if (VC == 4) {
                float4 t0 = *(const float4*)&T[(size_t)u0 * D + lane * 4];
                float4 t1 = *(const float4*)&T[(size_t)u1 * D + lane * 4];
                float4 t2 = *(const float4*)&T[(size_t)u2 * D + lane * 4];
                float4 t3 = *(const float4*)&T[(size_t)u3 * D + lane * 4];
                acc[0] += t0.x + t1.x + t2.x + t3.x;
                acc[1] += t0.y + t1.y + t2.y + t3.y;
                acc[2] += t0.z + t1.z + t2.z + t3.z;
                acc[3] += t0.w + t1.w + t2.w + t3.w;
            } else {
                float2 t0 = *(const float2*)&T[(size_t)u0 * D + lane * 2];
                float2 t1 = *(const float2*)&T[(size_t)u1 * D + lane * 2];
                float2 t2 = *(const float2*)&T[(size_t)u2 * D + lane * 2];
                float2 t3 = *(const float2*)&T[(size_t)u3 * D + lane * 2];
                acc[0] += t0.x + t1.x + t2.x + t3.x;
                acc[1] += t0.y + t1.y + t2.y + t3.y;
            }
        }
        for (; j < n; ++j) {
            int u = __shfl_sync(0xFFFFFFFFu, id, j);
            if (VC == 4) {
                float4 t0 = *(const float4*)&T[(size_t)u * D + lane * 4];
                acc[0] += t0.x; acc[1] += t0.y; acc[2] += t0.z; acc[3] += t0.w;
            } else {
                float2 t0 = *(const float2*)&T[(size_t)u * D + lane * 2];
                acc[0] += t0.x; acc[1] += t0.y;
            }
        }
    }

    const float nrm = g_in_norm[v];
    float val[VC];
    #pragma unroll
    for (int c = 0; c < VC; ++c)
        val[c] = fmaxf(acc[c] * nrm + bias[lane * VC + c], 0.0f);

    if (LN) {
        float s1 = 0.f, s2 = 0.f;
        #pragma unroll
        for (int c = 0; c < VC; ++c) { s1 += val[c]; s2 += val[c] * val[c]; }
        #pragma unroll
        for (int off = 16; off > 0; off >>= 1) {
            s1 += __shfl_xor_sync(0xFFFFFFFFu, s1, off);
            s2 += __shfl_xor_sync(0xFFFFFFFFu, s2, off);
        }
        float mu  = s1 * (1.0f / D);
        float var = s2 * (1.0f / D) - mu * mu;
        float r   = rsqrtf(var + LN_EPS);
        #pragma unroll
        for (int c = 0; c < VC; ++c)
            val[c] = (val[c] - mu) * r * ln_scale[lane * VC + c] + ln_bias[lane * VC + c];
    }

    if (VC == 4)
        *(float4*)&out[(size_t)v * D + lane * 4] = make_float4(val[0], val[1], val[2], val[3]);
    else
        *(float2*)&out[(size_t)v * D + lane * 2] = make_float2(val[0], val[1]);
}

// ---------------- launch ----------------
extern "C" void kernel_launch(void* const* d_in, const int* in_sizes, int n_in,
                              void* d_out, int out_size) {
    const float* x        = (const float*)d_in[0];
    const int*   src      = (const int*)  d_in[1];
    const int*   dst      = (const int*)  d_in[2];
    const float* W0       = (const float*)d_in[3];
    const float* b0       = (const float*)d_in[4];
    const float* W1       = (const float*)d_in[5];
    const float* b1       = (const float*)d_in[6];
    const float* W2       = (const float*)d_in[7];
    const float* b2       = (const float*)d_in[8];
    const float* ln_scale = (const float*)d_in[9];
    const float* ln_bias  = (const float*)d_in[10];
    float* out = (float*)d_out;

    float* tbuf; cudaGetSymbolAddress((void**)&tbuf, g_tbuf);
    float* hbuf; cudaGetSymbolAddress((void**)&hbuf, g_hbuf);

    const int EBLK = (N_EDGES + 255) / 256;
    const int NBLK = (N_NODES + 255) / 256;
    const int GBLK = (N_NODES + 63) / 64;
    const int ABLK = N_NODES / 8;                  // 6250, exact

    // smem: A frags 32KB + B frags (64KB | 32KB)
    const int SMEM_G128 = (4 * 8 * 32) * 16 * 2 + (8 * 16 * 32) * 8 * 2;  // 98304
    const int SMEM_G64  = (4 * 8 * 32) * 16 * 2 + (8 * 8  * 32) * 8 * 2;  // 65536
    cudaFuncSetAttribute(gemm_bf16_kernel<HID>,
                         cudaFuncAttributeMaxDynamicSharedMemorySize, SMEM_G128);
    cudaFuncSetAttribute(gemm_bf16_kernel<OUT_DIM>,
                         cudaFuncAttributeMaxDynamicSharedMemorySize, SMEM_G64);

    // graph preprocessing (recomputed every call; deterministic work)
    init_kernel  <<<NBLK, 256>>>();
    degree_kernel<<<EBLK, 256>>>(src, dst);
    norm_kernel  <<<NBLK, 256>>>();
    scan1_kernel <<<SCAN_NB, SCAN_BS>>>();
    scan2_kernel <<<1, SCAN_BS>>>();
    scan3_kernel <<<SCAN_NB, SCAN_BS>>>();
    fill_kernel  <<<EBLK, 256>>>(src, dst);

    // layer 0: x -> tbuf -> hbuf (relu + LN)
    gemm_bf16_kernel<HID><<<GBLK, 256, SMEM_G128>>>(x, W0, tbuf);
    aggregate_warp_kernel<HID, true><<<ABLK, 256>>>(tbuf, hbuf, b0, ln_scale, ln_bias);

    // layer 1: hbuf -> tbuf -> hbuf (relu + LN)
    gemm_bf16_kernel<HID><<<GBLK, 256, SMEM_G128>>>(hbuf, W1, tbuf);
    aggregate_warp_kernel<HID, true><<<ABLK, 256>>>(tbuf, hbuf, b1, ln_scale, ln_bias);

    // layer 2: hbuf -> tbuf -> out (relu, no LN)
    gemm_bf16_kernel<OUT_DIM><<<GBLK, 256, SMEM_G64>>>(hbuf, W2, tbuf);
    aggregate_warp_kernel<OUT_DIM, false><<<ABLK, 256>>>(tbuf, out, b2, ln_scale, ln_bias);

    (void)in_sizes; (void)n_in; (void)out_size;
}